// round 12
// baseline (speedup 1.0000x reference)
#include <cuda_runtime.h>
#include <cuda_fp16.h>
#include <math.h>
#include <stdint.h>

#define BATCH   2
#define SEQ     2048
#define DIM     2048
#define D_INNER 4096
#define D_STATE 128
#define N_HEADS 32
#define HEADDIM 128
#define D_CONV  4
#define CHUNK   256
#define NCHUNK  (SEQ/CHUNK)                       /* 8  */
#define NBCH    (BATCH*NCHUNK*N_HEADS)            /* 512 */
#define CONV_DIM (D_INNER + 2*D_STATE)            /* 4352 */
#define D_IN_PROJ (2*D_INNER + 2*D_STATE + N_HEADS) /* 8480 */
#define EPS 1e-5f

// ---------------- scratch (device globals, no allocation) ----------------
__device__ float g_zxbcdt[(size_t)BATCH*SEQ*D_IN_PROJ];
__device__ float g_xBC  [(size_t)BATCH*SEQ*CONV_DIM];
__device__ float g_dt   [(size_t)BATCH*SEQ*N_HEADS];
__device__ float g_dAcum[(size_t)BATCH*N_HEADS*SEQ];
__device__ float g_G    [(size_t)BATCH*NCHUNK*CHUNK*CHUNK];
__device__ float g_states[(size_t)NBCH*HEADDIM*D_STATE];
__device__ float g_y    [(size_t)BATCH*SEQ*D_INNER];
// fp16 operand mirrors
__device__ __half g_in_h  [(size_t)BATCH*SEQ*DIM];
__device__ __half g_win_h [(size_t)D_IN_PROJ*DIM];
__device__ __half g_wout_h[(size_t)DIM*D_INNER];
__device__ __half g_y_h   [(size_t)BATCH*SEQ*D_INNER];
__device__ __half g_bc_h  [(size_t)BATCH*SEQ*2*D_STATE];
// fp16 scan operands
__device__ __half g_xdt_h [(size_t)BATCH*SEQ*D_INNER];
__device__ __half g_LG    [(size_t)NBCH*CHUNK*CHUNK];
__device__ __half g_Bdec  [(size_t)NBCH*CHUNK*D_STATE];
__device__ __half g_Cexp  [(size_t)NBCH*CHUNK*D_STATE];
__device__ __half g_sin_h [(size_t)NBCH*HEADDIM*D_STATE];

__device__ __forceinline__ void cp16(uint32_t dst, const void* src, bool pred) {
    asm volatile("cp.async.cg.shared.global [%0], [%1], 16, %2;"
                 :: "r"(dst), "l"(src), "r"(pred ? 16 : 0));
}
__device__ __forceinline__ void ldsm4(uint32_t* r, uint32_t addr) {
    asm volatile("ldmatrix.sync.aligned.m8n8.x4.shared.b16 {%0,%1,%2,%3}, [%4];"
        : "=r"(r[0]), "=r"(r[1]), "=r"(r[2]), "=r"(r[3]) : "r"(addr));
}
// fast exp on FMA pipe: exp(x) for x<=0
__device__ __forceinline__ float fexp(float x) {
    float t = x * 1.4426950408889634f;
    t = fmaxf(t, -25.f);
    float fi = floorf(t);
    float f = t - fi;
    float p = 1.f + f*(0.69314718f + f*(0.24022651f + f*(0.05550411f
            + f*(0.00961813f + f*0.00133336f))));
    return p * __int_as_float(((int)fi + 127) << 23);
}

#define MMA16(acc, af, bf)                                                   \
    asm volatile(                                                            \
        "mma.sync.aligned.m16n8k16.row.col.f32.f16.f16.f32 "                 \
        "{%0,%1,%2,%3}, {%4,%5,%6,%7}, {%8,%9}, {%0,%1,%2,%3};"              \
        : "+f"(acc[0]), "+f"(acc[1]), "+f"(acc[2]), "+f"(acc[3])             \
        : "r"(af[0]), "r"(af[1]), "r"(af[2]), "r"(af[3]),                    \
          "r"(bf[0]), "r"(bf[1]))

// ================== fp16 mma.sync batched NT GEMM (projections) ===========
// BK=64, 3-stage cp.async, XOR-swizzled smem, ldmatrix, 1 barrier/iter.
#define GSTG (128*64*2)               /* 16384 B per operand-stage */
#define GSMEM (6*GSTG)                /* 98304 */
__global__ __launch_bounds__(256, 2)
void gemm_h(const __half* __restrict__ A, long lda, long sA,
            const __half* __restrict__ W, long ldb, long sB,
            float* __restrict__ C, long ldc, long sC,
            int M, int N, int K, const float* __restrict__ bias)
{
    extern __shared__ char smem[];
    int bz = blockIdx.z;
    const __half* Ab = A + (long)bz * sA;
    const __half* Wb = W + (long)bz * sB;
    float*        Cb = C + (long)bz * sC;
    int bm = blockIdx.y * 128, bn = blockIdx.x * 128;
    int tid  = threadIdx.x;
    int warp = tid >> 5, lane = tid & 31;
    int wm = warp >> 2, wn = warp & 3;
    int g  = lane >> 2, t4 = lane & 3;

    uint32_t sAu = (uint32_t)__cvta_generic_to_shared(smem);
    uint32_t sBu = sAu + 3*GSTG;

    int arow = lane & 15;
    int achk = lane >> 4;
    int brow = ((lane >> 4) << 3) + (lane & 7);
    int bchk = (lane >> 3) & 1;

    float acc[4][4][4];
    #pragma unroll
    for (int i = 0; i < 4; i++)
        #pragma unroll
        for (int j = 0; j < 4; j++)
            #pragma unroll
            for (int q = 0; q < 4; q++) acc[i][j][q] = 0.f;

    const int KT = K / 64;

    #define LOADTILE(st, k0)                                                  \
    do {                                                                      \
        _Pragma("unroll")                                                     \
        for (int it = 0; it < 4; it++) {                                      \
            int idx = tid + it*256;                                           \
            int row = idx >> 3, c8 = idx & 7;                                 \
            int sc = c8 ^ (row & 7);                                          \
            cp16(sAu + (st)*GSTG + row*128 + sc*16,                           \
                 &Ab[(long)(bm+row)*lda + (k0) + c8*8], true);                \
        }                                                                     \
        _Pragma("unroll")                                                     \
        for (int it = 0; it < 4; it++) {                                      \
            int idx = tid + it*256;                                           \
            int row = idx >> 3, c8 = idx & 7;                                 \
            int sc = c8 ^ (row & 7);                                          \
            int gn = bn + row; bool p = gn < N;                               \
            cp16(sBu + (st)*GSTG + row*128 + sc*16,                           \
                 &Wb[(long)(p ? gn : 0)*ldb + (k0) + c8*8], p);               \
        }                                                                     \
    } while (0)

    LOADTILE(0, 0);
    asm volatile("cp.async.commit_group;");
    if (KT > 1) LOADTILE(1, 64);
    asm volatile("cp.async.commit_group;");

    for (int kt = 0; kt < KT; kt++) {
        asm volatile("cp.async.wait_group 1;" ::: "memory");
        __syncthreads();    // also guarantees compute of kt-1 fully done
        if (kt + 2 < KT) LOADTILE((kt+2) % 3, (kt+2)*64);
        asm volatile("cp.async.commit_group;");

        int st = kt % 3;
        #pragma unroll
        for (int ks = 0; ks < 4; ks++) {
            uint32_t af[4][4], bf[4][2];
            #pragma unroll
            for (int mt = 0; mt < 4; mt++) {
                int r = wm*64 + mt*16 + arow;
                int chk = (ks*2 + achk) ^ (r & 7);
                ldsm4(af[mt], sAu + st*GSTG + r*128 + chk*16);
            }
            #pragma unroll
            for (int np = 0; np < 2; np++) {
                int r = wn*32 + np*16 + brow;
                int chk = (ks*2 + bchk) ^ (r & 7);
                uint32_t t[4];
                ldsm4(t, sBu + st*GSTG + r*128 + chk*16);
                bf[np*2  ][0] = t[0]; bf[np*2  ][1] = t[1];
                bf[np*2+1][0] = t[2]; bf[np*2+1][1] = t[3];
            }
            #pragma unroll
            for (int mt = 0; mt < 4; mt++)
                #pragma unroll
                for (int nt = 0; nt < 4; nt++)
                    MMA16(acc[mt][nt], af[mt], bf[nt]);
        }
        // no trailing barrier: next-iter top barrier covers the hazard
    }
    #undef LOADTILE

    #pragma unroll
    for (int mt = 0; mt < 4; mt++) {
        int row0 = bm + wm*64 + mt*16 + g;
        #pragma unroll
        for (int nt = 0; nt < 4; nt++) {
            int col0 = bn + wn*32 + nt*8 + 2*t4;
            if (col0 < N) {
                float b0 = bias ? bias[col0] : 0.f;
                Cb[(long)row0*ldc + col0] = acc[mt][nt][0] + b0;
                Cb[(long)(row0+8)*ldc + col0] = acc[mt][nt][2] + b0;
            }
            if (col0+1 < N) {
                float b1 = bias ? bias[col0+1] : 0.f;
                Cb[(long)row0*ldc + col0+1] = acc[mt][nt][1] + b1;
                Cb[(long)(row0+8)*ldc + col0+1] = acc[mt][nt][3] + b1;
            }
        }
    }
}

// =============== scan GEMMs: 128x128 tile, K-step 32, fp16 ================
// double-buffered smem, 1 barrier/iter
#define SS 42

struct ZIdx { int b, c, h; };
__device__ __forceinline__ ZIdx zdec(int z) {
    ZIdx r; r.h = z % N_HEADS; int bc = z / N_HEADS;
    r.c = bc % NCHUNK; r.b = bc / NCHUNK; return r;
}

template<int STAGEA, int STAGEB, int OUTMODE>
__device__ __forceinline__ void scan_gemm_core(
    const __half* Ag, long lda,
    const __half* Bg, long ldb,
    float* Cg, long ldc,
    int KT)
{
    __shared__ __half As[2][128][SS];
    __shared__ __half Bs[2][128][SS];
    int tid = threadIdx.x;
    int warp = tid >> 5, lane = tid & 31;
    int wm = warp >> 2, wn = warp & 3;
    int g = lane >> 2, t4 = lane & 3;

    float acc[4][4][4];
    #pragma unroll
    for (int i = 0; i < 4; i++)
        #pragma unroll
        for (int j = 0; j < 4; j++)
            #pragma unroll
            for (int q = 0; q < 4; q++) acc[i][j][q] = 0.f;

    for (int kt = 0; kt < KT; kt++) {
        int k0 = kt * 32;
        int buf = kt & 1;
        if (STAGEA == 0) {
            #pragma unroll
            for (int i = 0; i < 8; i++) {
                int idx = tid + i*256;
                int row = idx >> 4, c2 = (idx & 15) * 2;
                *(__half2*)&As[buf][row][c2] = *(const __half2*)&Ag[(long)row*lda + k0 + c2];
            }
        } else {
            #pragma unroll
            for (int i = 0; i < 8; i++) {
                int idx = tid + i*256;
                int k = idx >> 6, m2 = (idx & 63) * 2;
                __half2 v = *(const __half2*)&Ag[(long)(k0+k)*lda + m2];
                As[buf][m2  ][k] = __low2half(v);
                As[buf][m2+1][k] = __high2half(v);
            }
        }
        if (STAGEB == 0) {
            #pragma unroll
            for (int i = 0; i < 8; i++) {
                int idx = tid + i*256;
                int row = idx >> 4, c2 = (idx & 15) * 2;
                *(__half2*)&Bs[buf][row][c2] = *(const __half2*)&Bg[(long)row*ldb + k0 + c2];
            }
        } else {
            #pragma unroll
            for (int i = 0; i < 8; i++) {
                int idx = tid + i*256;
                int k = idx >> 6, n2 = (idx & 63) * 2;
                __half2 v = *(const __half2*)&Bg[(long)(k0+k)*ldb + n2];
                Bs[buf][n2  ][k] = __low2half(v);
                Bs[buf][n2+1][k] = __high2half(v);
            }
        }
        __syncthreads();
        #pragma unroll
        for (int ks = 0; ks < 2; ks++) {
            int kb = ks * 16;
            uint32_t af[4][4], bf[4][2];
            #pragma unroll
            for (int mt = 0; mt < 4; mt++) {
                int r0 = wm*64 + mt*16 + g;
                af[mt][0] = *(const uint32_t*)&As[buf][r0  ][kb + t4*2    ];
                af[mt][1] = *(const uint32_t*)&As[buf][r0+8][kb + t4*2    ];
                af[mt][2] = *(const uint32_t*)&As[buf][r0  ][kb + t4*2 + 8];
                af[mt][3] = *(const uint32_t*)&As[buf][r0+8][kb + t4*2 + 8];
            }
            #pragma unroll
            for (int nt = 0; nt < 4; nt++) {
                int cc = wn*32 + nt*8 + g;
                bf[nt][0] = *(const uint32_t*)&Bs[buf][cc][kb + t4*2    ];
                bf[nt][1] = *(const uint32_t*)&Bs[buf][cc][kb + t4*2 + 8];
            }
            #pragma unroll
            for (int mt = 0; mt < 4; mt++)
                #pragma unroll
                for (int nt = 0; nt < 4; nt++)
                    MMA16(acc[mt][nt], af[mt], bf[nt]);
        }
        // no trailing barrier: next iter fills the other buffer;
        // its __syncthreads orders reuse of this one.
    }
    #pragma unroll
    for (int mt = 0; mt < 4; mt++) {
        int row0 = wm*64 + mt*16 + g;
        #pragma unroll
        for (int nt = 0; nt < 4; nt++) {
            int col0 = wn*32 + nt*8 + 2*t4;
            if (OUTMODE == 2) {
                Cg[(long)row0*ldc + col0  ] += acc[mt][nt][0];
                Cg[(long)row0*ldc + col0+1] += acc[mt][nt][1];
                Cg[(long)(row0+8)*ldc + col0  ] += acc[mt][nt][2];
                Cg[(long)(row0+8)*ldc + col0+1] += acc[mt][nt][3];
            } else {
                Cg[(long)row0*ldc + col0  ] = acc[mt][nt][0];
                Cg[(long)row0*ldc + col0+1] = acc[mt][nt][1];
                Cg[(long)(row0+8)*ldc + col0  ] = acc[mt][nt][2];
                Cg[(long)(row0+8)*ldc + col0+1] = acc[mt][nt][3];
            }
        }
    }
}

__global__ __launch_bounds__(256)
void k_ydiag2()
{
    int z = blockIdx.x, bm = blockIdx.y * 128;
    ZIdx zi = zdec(z);
    long brow = (long)zi.b*SEQ + zi.c*CHUNK;
    const __half* Ag = g_LG + (long)z*CHUNK*CHUNK + (long)bm*CHUNK;
    const __half* Bg = g_xdt_h + brow*D_INNER + zi.h*HEADDIM;
    float* Cg = g_y + (brow + bm)*D_INNER + zi.h*HEADDIM;
    int KT = (bm + 128) / 32;
    scan_gemm_core<0,1,0>(Ag, CHUNK, Bg, D_INNER, Cg, D_INNER, KT);
}

__global__ __launch_bounds__(256)
void k_states2()
{
    int z = blockIdx.x;
    ZIdx zi = zdec(z);
    long brow = (long)zi.b*SEQ + zi.c*CHUNK;
    const __half* Ag = g_xdt_h + brow*D_INNER + zi.h*HEADDIM;
    const __half* Bg = g_Bdec + (long)z*CHUNK*D_STATE;
    float* Cg = g_states + (long)z*HEADDIM*D_STATE;
    scan_gemm_core<1,1,1>(Ag, D_INNER, Bg, D_STATE, Cg, D_STATE, CHUNK/32);
}

__global__ __launch_bounds__(256)
void k_yoff2()
{
    int z = blockIdx.x, bm = blockIdx.y * 128;
    ZIdx zi = zdec(z);
    long brow = (long)zi.b*SEQ + zi.c*CHUNK;
    const __half* Ag = g_Cexp + (long)z*CHUNK*D_STATE + (long)bm*D_STATE;
    const __half* Bg = g_sin_h + (long)z*HEADDIM*D_STATE;
    float* Cg = g_y + (brow + bm)*D_INNER + zi.h*HEADDIM;
    scan_gemm_core<0,0,2>(Ag, D_STATE, Bg, D_STATE, Cg, D_INNER, D_STATE/32);
}

// ---------------- prep kernels --------------------------------------------
__global__ __launch_bounds__(256)
void k_prep_xdt()
{
    long i = (long)blockIdx.x * 256 + threadIdx.x;
    long n2 = (long)BATCH*SEQ*D_INNER/2;
    long stride = (long)gridDim.x * 256;
    for (; i < n2; i += stride) {
        long d2 = i % (D_INNER/2);
        long bs = i / (D_INNER/2);
        int d = (int)d2 * 2;
        int h = d >> 7;
        float dt = g_dt[bs*N_HEADS + h];
        float v0 = g_xBC[bs*CONV_DIM + d]     * dt;
        float v1 = g_xBC[bs*CONV_DIM + d + 1] * dt;
        *(__half2*)&g_xdt_h[bs*D_INNER + d] = __floats2half2_rn(v0, v1);
    }
}

__global__ __launch_bounds__(256)
void k_prep_lg()
{
    int z = blockIdx.x, lt = blockIdx.y;
    ZIdx zi = zdec(z);
    int bc = z / N_HEADS;
    const float* cum = g_dAcum + ((long)zi.b*N_HEADS + zi.h)*SEQ + zi.c*CHUNK;
    __shared__ float cs[CHUNK];
    if (threadIdx.x < CHUNK) cs[threadIdx.x] = cum[threadIdx.x];
    __syncthreads();
    const float* G = g_G + (long)bc*CHUNK*CHUNK;
    __half* LG = g_LG + (long)z*CHUNK*CHUNK;
    int tid = threadIdx.x;
    #pragma unroll 4
    for (int j = 0; j < 64; j++) {
        int lin = tid + j*256;
        int l = lt*64 + (lin >> 8);
        int s = lin & 255;
        float v = 0.f;
        if (s <= l) v = G[l*CHUNK + s] * fexp(cs[l] - cs[s]);
        LG[l*CHUNK + s] = __float2half_rn(v);
    }
}

__global__ __launch_bounds__(256)
void k_prep_bc()
{
    int z = blockIdx.x;
    ZIdx zi = zdec(z);
    const float* cum = g_dAcum + ((long)zi.b*N_HEADS + zi.h)*SEQ + zi.c*CHUNK;
    __shared__ float fb[CHUNK], fc[CHUNK];
    if (threadIdx.x < CHUNK) {
        float cl = cum[threadIdx.x];
        fb[threadIdx.x] = fexp(cum[CHUNK-1] - cl);
        fc[threadIdx.x] = fexp(cl);
    }
    __syncthreads();
    long brow = (long)zi.b*SEQ + zi.c*CHUNK;
    __half* Bd = g_Bdec + (long)z*CHUNK*D_STATE;
    __half* Ce = g_Cexp + (long)z*CHUNK*D_STATE;
    int tid = threadIdx.x;
    #pragma unroll 4
    for (int j = 0; j < 128; j++) {
        int lin = tid + j*256;
        int l = lin >> 7, n = lin & 127;
        long bs = brow + l;
        float Bv = __half2float(g_bc_h[bs*(2*D_STATE) + n]);
        float Cv = __half2float(g_bc_h[bs*(2*D_STATE) + D_STATE + n]);
        Bd[lin] = __float2half_rn(Bv * fb[l]);
        Ce[lin] = __float2half_rn(Cv * fc[l]);
    }
}

__global__ __launch_bounds__(256)
void k_tohalf(const float* __restrict__ src, __half* __restrict__ dst, long n2)
{
    long i = (long)blockIdx.x * 256 + threadIdx.x;
    long stride = (long)gridDim.x * 256;
    for (; i < n2; i += stride) {
        float2 v = *reinterpret_cast<const float2*>(src + i*2);
        *reinterpret_cast<__half2*>(dst + i*2) = __floats2half2_rn(v.x, v.y);
    }
}

// ---------------- exact fp32 dt projection + softplus ---------------------
__global__ __launch_bounds__(256)
void k_dtproj(const float* __restrict__ inputs,
              const float* __restrict__ in_proj_w,
              const float* __restrict__ in_proj_b,
              const float* __restrict__ dt_bias)
{
    __shared__ float xs[32][133];
    __shared__ float ws[32][133];
    int t = threadIdx.x;
    long r0 = (long)blockIdx.x * 32;
    int r = t >> 3;
    int hb = (t & 7) * 4;
    const float* Wdt = in_proj_w + (size_t)(D_INNER + CONV_DIM) * DIM;
    float acc[4] = {0.f, 0.f, 0.f, 0.f};
    for (int k0 = 0; k0 < DIM; k0 += 128) {
        #pragma unroll
        for (int i = 0; i < 4; i++) {
            int idx = t + i*256;
            int row = idx >> 5, c4 = (idx & 31) * 4;
            float4 v = *reinterpret_cast<const float4*>(&inputs[(r0+row)*DIM + k0 + c4]);
            xs[row][c4] = v.x; xs[row][c4+1] = v.y; xs[row][c4+2] = v.z; xs[row][c4+3] = v.w;
            float4 w = *reinterpret_cast<const float4*>(&Wdt[(size_t)row*DIM + k0 + c4]);
            ws[row][c4] = w.x; ws[row][c4+1] = w.y; ws[row][c4+2] = w.z; ws[row][c4+3] = w.w;
        }
        __syncthreads();
        #pragma unroll 8
        for (int k = 0; k < 128; k++) {
            float xv = xs[r][k];
            #pragma unroll
            for (int j = 0; j < 4; j++)
                acc[j] = fmaf(xv, ws[hb+j][k], acc[j]);
        }
        __syncthreads();
    }
    #pragma unroll
    for (int j = 0; j < 4; j++) {
        int h = hb + j;
        float x = acc[j] + in_proj_b[D_INNER + CONV_DIM + h] + dt_bias[h];
        g_dt[(r0 + r)*N_HEADS + h] = (x > 20.f) ? x : log1pf(expf(x));
    }
}

// ---------------- causal depthwise conv + SiLU ----------------------------
__global__ __launch_bounds__(256)
void k_conv(const float* __restrict__ conv_w, const float* __restrict__ conv_b)
{
    long i = (long)blockIdx.x * 256 + threadIdx.x;
    if (i >= (long)BATCH*SEQ*CONV_DIM) return;
    int c = (int)(i % CONV_DIM);
    long bs = i / CONV_DIM;
    int s = (int)(bs % SEQ);
    int b = (int)(bs / SEQ);
    float acc = conv_b[c];
    #pragma unroll
    for (int k = 0; k < D_CONV; k++) {
        int sp = s - (D_CONV-1) + k;
        if (sp >= 0)
            acc = fmaf(g_zxbcdt[((long)b*SEQ + sp)*D_IN_PROJ + D_INNER + c],
                       conv_w[c*D_CONV + k], acc);
    }
    float v = acc / (1.f + expf(-acc));
    g_xBC[i] = v;
    if (c >= D_INNER)
        g_bc_h[bs*(2*D_STATE) + (c - D_INNER)] = __float2half_rn(v);
}

// ---------------- chunk-local inclusive cumsum of A*dt --------------------
__global__ __launch_bounds__(CHUNK)
void k_cumsum(const float* __restrict__ A_log)
{
    int bz = blockIdx.x;
    int c = bz % NCHUNK; int bh = bz / NCHUNK;
    int h = bh % N_HEADS; int b = bh / N_HEADS;
    int l = threadIdx.x;
    int sg = c*CHUNK + l;
    float A = -expf(A_log[h]);
    float val = A * g_dt[((long)b*SEQ + sg)*N_HEADS + h];
    __shared__ float buf[CHUNK];
    buf[l] = val; __syncthreads();
    for (int off = 1; off < CHUNK; off <<= 1) {
        float t = (l >= off) ? buf[l-off] : 0.f;
        __syncthreads();
        buf[l] += t;
        __syncthreads();
    }
    g_dAcum[((long)b*N_HEADS + h)*SEQ + sg] = buf[l];
}

// ---------------- inter-chunk recurrence (-> Sin fp16) --------------------
// grid (BATCH*N_HEADS, 8): full-chip parallel over pn slices
__global__ __launch_bounds__(256)
void k_chunkrec()
{
    int bh = blockIdx.x;
    int h = bh % N_HEADS; int b = bh / N_HEADS;
    const float* cum = g_dAcum + (long)bh*SEQ;
    float csum[NCHUNK];
    #pragma unroll
    for (int c = 0; c < NCHUNK; c++) csum[c] = expf(cum[c*CHUNK + CHUNK-1]);
    int pn0 = blockIdx.y * (HEADDIM*D_STATE/8);
    #pragma unroll
    for (int j = 0; j < (HEADDIM*D_STATE/8)/256; j++) {
        int pn = pn0 + j*256 + threadIdx.x;
        float carry = 0.f;
        #pragma unroll
        for (int c = 0; c < NCHUNK; c++) {
            long z = ((long)b*NCHUNK + c)*N_HEADS + h;
            long idx = z*HEADDIM*D_STATE + pn;
            g_sin_h[idx] = __float2half_rn(carry);
            carry = carry * csum[c] + g_states[idx];
        }
    }
}

// ---------------- gate (y + D*x) * silu(z) + RMSNorm -> fp16 --------------
__global__ __launch_bounds__(256)
void k_gatenorm(const float* __restrict__ norm_w, const float* __restrict__ Dv)
{
    long row = blockIdx.x;
    const float* zrow = g_zxbcdt + row*D_IN_PROJ;
    const float* xrow = g_xBC + row*CONV_DIM;
    float* yrow = g_y + row*D_INNER;
    __half* yh = g_y_h + row*D_INNER;
    float vals[16];
    float local = 0.f;
    #pragma unroll
    for (int i = 0; i < 16; i++) {
        int d = threadIdx.x + i*256;
        float z = zrow[d];
        float v = (yrow[d] + Dv[d >> 7] * xrow[d]) * (z / (1.f + expf(-z)));
        vals[i] = v;
        local += v * v;
    }
    __shared__ float red[256];
    red[threadIdx.x] = local; __syncthreads();
    for (int off = 128; off > 0; off >>= 1) {
        if (threadIdx.x < off) red[threadIdx.x] += red[threadIdx.x + off];
        __syncthreads();
    }
    float scale = rsqrtf(red[0] / D_INNER + EPS);
    #pragma unroll
    for (int i = 0; i < 16; i++) {
        int d = threadIdx.x + i*256;
        yh[d] = __float2half_rn(vals[i] * scale * norm_w[d]);
    }
}

// --------------------------------------------------------------------------
extern "C" void kernel_launch(void* const* d_in, const int* in_sizes, int n_in,
                              void* d_out, int out_size)
{
    const float* inputs     = (const float*)d_in[0];
    const float* in_proj_w  = (const float*)d_in[1];
    const float* in_proj_b  = (const float*)d_in[2];
    const float* out_proj_w = (const float*)d_in[3];
    const float* out_proj_b = (const float*)d_in[4];
    const float* conv_w     = (const float*)d_in[5];
    const float* conv_b     = (const float*)d_in[6];
    const float* dt_bias    = (const float*)d_in[7];
    const float* A_log      = (const float*)d_in[8];
    const float* Dv         = (const float*)d_in[9];
    const float* norm_w     = (const float*)d_in[10];
    float* out = (float*)d_out;

    float *zx, *Gp;
    __half *inh, *winh, *wouth, *yh, *bch;
    cudaGetSymbolAddress((void**)&zx,    g_zxbcdt);
    cudaGetSymbolAddress((void**)&Gp,    g_G);
    cudaGetSymbolAddress((void**)&inh,   g_in_h);
    cudaGetSymbolAddress((void**)&winh,  g_win_h);
    cudaGetSymbolAddress((void**)&wouth, g_wout_h);
    cudaGetSymbolAddress((void**)&yh,    g_y_h);
    cudaGetSymbolAddress((void**)&bch,   g_bc_h);

    cudaFuncSetAttribute(gemm_h, cudaFuncAttributeMaxDynamicSharedMemorySize, GSMEM);

    const int M = BATCH * SEQ;     // 4096

    // 0) fp16 mirrors
    k_tohalf<<<2048, 256>>>(inputs,     inh,   (long)M*DIM/2);
    k_tohalf<<<2048, 256>>>(in_proj_w,  winh,  (long)D_IN_PROJ*DIM/2);
    k_tohalf<<<2048, 256>>>(out_proj_w, wouth, (long)DIM*D_INNER/2);

    // 1) in_proj
    {
        dim3 grid((D_IN_PROJ + 127)/128, M/128, 1);
        gemm_h<<<grid, 256, GSMEM>>>(inh, DIM, 0, winh, DIM, 0,
                              zx, D_IN_PROJ, 0, M, D_IN_PROJ, DIM, in_proj_b);
    }
    // 2) exact dt projection
    k_dtproj<<<M/32, 256>>>(inputs, in_proj_w, in_proj_b, dt_bias);
    // 3) conv + silu
    k_conv<<<(int)(((long)BATCH*SEQ*CONV_DIM + 255)/256), 256>>>(conv_w, conv_b);
    // 4) cumsum
    k_cumsum<<<BATCH*N_HEADS*NCHUNK, CHUNK>>>(A_log);
    // 5) G = C @ B^T per (b,c)
    {
        dim3 grid(CHUNK/128, CHUNK/128, BATCH*NCHUNK);
        gemm_h<<<grid, 256, GSMEM>>>(bch + D_STATE, 2*D_STATE, (long)CHUNK*2*D_STATE,
                              bch,           2*D_STATE, (long)CHUNK*2*D_STATE,
                              Gp, CHUNK, (long)CHUNK*CHUNK,
                              CHUNK, CHUNK, D_STATE, nullptr);
    }
    // 6) preps
    k_prep_xdt<<<2048, 256>>>();
    {
        dim3 grid(NBCH, CHUNK/64);
        k_prep_lg<<<grid, 256>>>();
    }
    k_prep_bc<<<NBCH, 256>>>();
    // 7) Y_diag (tensor)
    {
        dim3 grid(NBCH, CHUNK/128);
        k_ydiag2<<<grid, 256>>>();
    }
    // 8) states (tensor)
    k_states2<<<NBCH, 256>>>();
    // 9) inter-chunk recurrence -> Sin fp16 (full-chip)
    {
        dim3 grid(BATCH*N_HEADS, 8);
        k_chunkrec<<<grid, 256>>>();
    }
    // 10) Y_off += (tensor)
    {
        dim3 grid(NBCH, CHUNK/128);
        k_yoff2<<<grid, 256>>>();
    }
    // 11) gate + D*x + RMSNorm -> fp16
    k_gatenorm<<<BATCH*SEQ, 256>>>(norm_w, Dv);
    // 12) out_proj
    {
        dim3 grid(DIM/128, M/128, 1);
        gemm_h<<<grid, 256, GSMEM>>>(yh, D_INNER, 0, wouth, D_INNER, 0,
                              out, DIM, 0, M, DIM, D_INNER, out_proj_b);
    }
}

// round 13
// speedup vs baseline: 1.4331x; 1.4331x over previous
#include <cuda_runtime.h>
#include <cuda_fp16.h>
#include <math.h>
#include <stdint.h>

#define BATCH   2
#define SEQ     2048
#define DIM     2048
#define D_INNER 4096
#define D_STATE 128
#define N_HEADS 32
#define HEADDIM 128
#define D_CONV  4
#define CHUNK   256
#define NCHUNK  (SEQ/CHUNK)                       /* 8  */
#define NBCH    (BATCH*NCHUNK*N_HEADS)            /* 512 */
#define CONV_DIM (D_INNER + 2*D_STATE)            /* 4352 */
#define D_IN_PROJ (2*D_INNER + 2*D_STATE + N_HEADS) /* 8480 */
#define EPS 1e-5f

// ---------------- scratch (device globals, no allocation) ----------------
__device__ float g_zxbcdt[(size_t)BATCH*SEQ*D_IN_PROJ];
__device__ float g_xBC  [(size_t)BATCH*SEQ*CONV_DIM];
__device__ float g_dt   [(size_t)BATCH*SEQ*N_HEADS];
__device__ float g_dAcum[(size_t)BATCH*N_HEADS*SEQ];
__device__ float g_G    [(size_t)BATCH*NCHUNK*CHUNK*CHUNK];
__device__ float g_states[(size_t)NBCH*HEADDIM*D_STATE];
__device__ float g_y    [(size_t)BATCH*SEQ*D_INNER];
// fp16 operand mirrors
__device__ __half g_in_h  [(size_t)BATCH*SEQ*DIM];
__device__ __half g_win_h [(size_t)D_IN_PROJ*DIM];
__device__ __half g_wout_h[(size_t)DIM*D_INNER];
__device__ __half g_y_h   [(size_t)BATCH*SEQ*D_INNER];
__device__ __half g_bc_h  [(size_t)BATCH*SEQ*2*D_STATE];
// fp16 scan operands
__device__ __half g_xdt_h [(size_t)BATCH*SEQ*D_INNER];
__device__ __half g_LG    [(size_t)NBCH*CHUNK*CHUNK];
__device__ __half g_Bdec  [(size_t)NBCH*CHUNK*D_STATE];
__device__ __half g_Cexp  [(size_t)NBCH*CHUNK*D_STATE];
__device__ __half g_sin_h [(size_t)NBCH*HEADDIM*D_STATE];

__device__ __forceinline__ void cp16(uint32_t dst, const void* src, bool pred) {
    asm volatile("cp.async.cg.shared.global [%0], [%1], 16, %2;"
                 :: "r"(dst), "l"(src), "r"(pred ? 16 : 0));
}
__device__ __forceinline__ void ldsm4(uint32_t* r, uint32_t addr) {
    asm volatile("ldmatrix.sync.aligned.m8n8.x4.shared.b16 {%0,%1,%2,%3}, [%4];"
        : "=r"(r[0]), "=r"(r[1]), "=r"(r[2]), "=r"(r[3]) : "r"(addr));
}
// fast exp on FMA pipe: exp(x) for x<=0
__device__ __forceinline__ float fexp(float x) {
    float t = x * 1.4426950408889634f;
    t = fmaxf(t, -25.f);
    float fi = floorf(t);
    float f = t - fi;
    float p = 1.f + f*(0.69314718f + f*(0.24022651f + f*(0.05550411f
            + f*(0.00961813f + f*0.00133336f))));
    return p * __int_as_float(((int)fi + 127) << 23);
}

#define MMA16(acc, af, bf)                                                   \
    asm volatile(                                                            \
        "mma.sync.aligned.m16n8k16.row.col.f32.f16.f16.f32 "                 \
        "{%0,%1,%2,%3}, {%4,%5,%6,%7}, {%8,%9}, {%0,%1,%2,%3};"              \
        : "+f"(acc[0]), "+f"(acc[1]), "+f"(acc[2]), "+f"(acc[3])             \
        : "r"(af[0]), "r"(af[1]), "r"(af[2]), "r"(af[3]),                    \
          "r"(bf[0]), "r"(bf[1]))

// ================== fp16 mma.sync batched NT GEMM (projections) ===========
// BK=64, 3-stage cp.async, XOR-swizzled smem (no pad), ldmatrix fragments.
// Row = 128B (64 halves); 16B chunk index swizzled by (row & 7).
// Smem: 2 ops x 3 stages x 16384 B = 98304 B -> 2 CTAs/SM.
#define GSTG (128*64*2)               /* 16384 B per operand-stage */
#define GSMEM (6*GSTG)                /* 98304 */
__global__ __launch_bounds__(256, 2)
void gemm_h(const __half* __restrict__ A, long lda, long sA,
            const __half* __restrict__ W, long ldb, long sB,
            float* __restrict__ C, long ldc, long sC,
            int M, int N, int K, const float* __restrict__ bias)
{
    extern __shared__ char smem[];
    int bz = blockIdx.z;
    const __half* Ab = A + (long)bz * sA;
    const __half* Wb = W + (long)bz * sB;
    float*        Cb = C + (long)bz * sC;
    int bm = blockIdx.y * 128, bn = blockIdx.x * 128;
    int tid  = threadIdx.x;
    int warp = tid >> 5, lane = tid & 31;
    int wm = warp >> 2, wn = warp & 3;
    int g  = lane >> 2, t4 = lane & 3;

    uint32_t sAu = (uint32_t)__cvta_generic_to_shared(smem);
    uint32_t sBu = sAu + 3*GSTG;

    int arow = lane & 15;
    int achk = lane >> 4;
    int brow = ((lane >> 4) << 3) + (lane & 7);
    int bchk = (lane >> 3) & 1;

    float acc[4][4][4];
    #pragma unroll
    for (int i = 0; i < 4; i++)
        #pragma unroll
        for (int j = 0; j < 4; j++)
            #pragma unroll
            for (int q = 0; q < 4; q++) acc[i][j][q] = 0.f;

    const int KT = K / 64;

    #define LOADTILE(st, k0)                                                  \
    do {                                                                      \
        _Pragma("unroll")                                                     \
        for (int it = 0; it < 4; it++) {                                      \
            int idx = tid + it*256;                                           \
            int row = idx >> 3, c8 = idx & 7;                                 \
            int sc = c8 ^ (row & 7);                                          \
            cp16(sAu + (st)*GSTG + row*128 + sc*16,                           \
                 &Ab[(long)(bm+row)*lda + (k0) + c8*8], true);                \
        }                                                                     \
        _Pragma("unroll")                                                     \
        for (int it = 0; it < 4; it++) {                                      \
            int idx = tid + it*256;                                           \
            int row = idx >> 3, c8 = idx & 7;                                 \
            int sc = c8 ^ (row & 7);                                          \
            int gn = bn + row; bool p = gn < N;                               \
            cp16(sBu + (st)*GSTG + row*128 + sc*16,                           \
                 &Wb[(long)(p ? gn : 0)*ldb + (k0) + c8*8], p);               \
        }                                                                     \
    } while (0)

    LOADTILE(0, 0);
    asm volatile("cp.async.commit_group;");
    if (KT > 1) LOADTILE(1, 64);
    asm volatile("cp.async.commit_group;");

    for (int kt = 0; kt < KT; kt++) {
        asm volatile("cp.async.wait_group 1;" ::: "memory");
        __syncthreads();
        if (kt + 2 < KT) LOADTILE((kt+2) % 3, (kt+2)*64);
        asm volatile("cp.async.commit_group;");

        int st = kt % 3;
        #pragma unroll
        for (int ks = 0; ks < 4; ks++) {
            uint32_t af[4][4], bf[4][2];
            #pragma unroll
            for (int mt = 0; mt < 4; mt++) {
                int r = wm*64 + mt*16 + arow;
                int chk = (ks*2 + achk) ^ (r & 7);
                ldsm4(af[mt], sAu + st*GSTG + r*128 + chk*16);
            }
            #pragma unroll
            for (int np = 0; np < 2; np++) {
                int r = wn*32 + np*16 + brow;
                int chk = (ks*2 + bchk) ^ (r & 7);
                uint32_t t[4];
                ldsm4(t, sBu + st*GSTG + r*128 + chk*16);
                bf[np*2  ][0] = t[0]; bf[np*2  ][1] = t[1];
                bf[np*2+1][0] = t[2]; bf[np*2+1][1] = t[3];
            }
            #pragma unroll
            for (int mt = 0; mt < 4; mt++)
                #pragma unroll
                for (int nt = 0; nt < 4; nt++)
                    MMA16(acc[mt][nt], af[mt], bf[nt]);
        }
        __syncthreads();
    }
    #undef LOADTILE

    #pragma unroll
    for (int mt = 0; mt < 4; mt++) {
        int row0 = bm + wm*64 + mt*16 + g;
        #pragma unroll
        for (int nt = 0; nt < 4; nt++) {
            int col0 = bn + wn*32 + nt*8 + 2*t4;
            if (col0 < N) {
                float b0 = bias ? bias[col0] : 0.f;
                Cb[(long)row0*ldc + col0] = acc[mt][nt][0] + b0;
                Cb[(long)(row0+8)*ldc + col0] = acc[mt][nt][2] + b0;
            }
            if (col0+1 < N) {
                float b1 = bias ? bias[col0+1] : 0.f;
                Cb[(long)row0*ldc + col0+1] = acc[mt][nt][1] + b1;
                Cb[(long)(row0+8)*ldc + col0+1] = acc[mt][nt][3] + b1;
            }
        }
    }
}

// =============== scan GEMMs: 128x128 tile, K-step 32, fp16 ================
#define SS 42

struct ZIdx { int b, c, h; };
__device__ __forceinline__ ZIdx zdec(int z) {
    ZIdx r; r.h = z % N_HEADS; int bc = z / N_HEADS;
    r.c = bc % NCHUNK; r.b = bc / NCHUNK; return r;
}

template<int STAGEA, int STAGEB, int OUTMODE>
__device__ __forceinline__ void scan_gemm_core(
    const __half* Ag, long lda,
    const __half* Bg, long ldb,
    float* Cg, long ldc,
    int KT)
{
    __shared__ __half As[128][SS];
    __shared__ __half Bs[128][SS];
    int tid = threadIdx.x;
    int warp = tid >> 5, lane = tid & 31;
    int wm = warp >> 2, wn = warp & 3;
    int g = lane >> 2, t4 = lane & 3;

    float acc[4][4][4];
    #pragma unroll
    for (int i = 0; i < 4; i++)
        #pragma unroll
        for (int j = 0; j < 4; j++)
            #pragma unroll
            for (int q = 0; q < 4; q++) acc[i][j][q] = 0.f;

    for (int kt = 0; kt < KT; kt++) {
        int k0 = kt * 32;
        if (STAGEA == 0) {
            #pragma unroll
            for (int i = 0; i < 8; i++) {
                int idx = tid + i*256;
                int row = idx >> 4, c2 = (idx & 15) * 2;
                *(__half2*)&As[row][c2] = *(const __half2*)&Ag[(long)row*lda + k0 + c2];
            }
        } else {
            #pragma unroll
            for (int i = 0; i < 8; i++) {
                int idx = tid + i*256;
                int k = idx >> 6, m2 = (idx & 63) * 2;
                __half2 v = *(const __half2*)&Ag[(long)(k0+k)*lda + m2];
                As[m2  ][k] = __low2half(v);
                As[m2+1][k] = __high2half(v);
            }
        }
        if (STAGEB == 0) {
            #pragma unroll
            for (int i = 0; i < 8; i++) {
                int idx = tid + i*256;
                int row = idx >> 4, c2 = (idx & 15) * 2;
                *(__half2*)&Bs[row][c2] = *(const __half2*)&Bg[(long)row*ldb + k0 + c2];
            }
        } else {
            #pragma unroll
            for (int i = 0; i < 8; i++) {
                int idx = tid + i*256;
                int k = idx >> 6, n2 = (idx & 63) * 2;
                __half2 v = *(const __half2*)&Bg[(long)(k0+k)*ldb + n2];
                Bs[n2  ][k] = __low2half(v);
                Bs[n2+1][k] = __high2half(v);
            }
        }
        __syncthreads();
        #pragma unroll
        for (int ks = 0; ks < 2; ks++) {
            int kb = ks * 16;
            uint32_t af[4][4], bf[4][2];
            #pragma unroll
            for (int mt = 0; mt < 4; mt++) {
                int r0 = wm*64 + mt*16 + g;
                af[mt][0] = *(const uint32_t*)&As[r0  ][kb + t4*2    ];
                af[mt][1] = *(const uint32_t*)&As[r0+8][kb + t4*2    ];
                af[mt][2] = *(const uint32_t*)&As[r0  ][kb + t4*2 + 8];
                af[mt][3] = *(const uint32_t*)&As[r0+8][kb + t4*2 + 8];
            }
            #pragma unroll
            for (int nt = 0; nt < 4; nt++) {
                int cc = wn*32 + nt*8 + g;
                bf[nt][0] = *(const uint32_t*)&Bs[cc][kb + t4*2    ];
                bf[nt][1] = *(const uint32_t*)&Bs[cc][kb + t4*2 + 8];
            }
            #pragma unroll
            for (int mt = 0; mt < 4; mt++)
                #pragma unroll
                for (int nt = 0; nt < 4; nt++)
                    MMA16(acc[mt][nt], af[mt], bf[nt]);
        }
        __syncthreads();
    }
    #pragma unroll
    for (int mt = 0; mt < 4; mt++) {
        int row0 = wm*64 + mt*16 + g;
        #pragma unroll
        for (int nt = 0; nt < 4; nt++) {
            int col0 = wn*32 + nt*8 + 2*t4;
            if (OUTMODE == 2) {
                Cg[(long)row0*ldc + col0  ] += acc[mt][nt][0];
                Cg[(long)row0*ldc + col0+1] += acc[mt][nt][1];
                Cg[(long)(row0+8)*ldc + col0  ] += acc[mt][nt][2];
                Cg[(long)(row0+8)*ldc + col0+1] += acc[mt][nt][3];
            } else {
                Cg[(long)row0*ldc + col0  ] = acc[mt][nt][0];
                Cg[(long)row0*ldc + col0+1] = acc[mt][nt][1];
                Cg[(long)(row0+8)*ldc + col0  ] = acc[mt][nt][2];
                Cg[(long)(row0+8)*ldc + col0+1] = acc[mt][nt][3];
            }
        }
    }
}

__global__ __launch_bounds__(256)
void k_ydiag2()
{
    int z = blockIdx.x, bm = blockIdx.y * 128;
    ZIdx zi = zdec(z);
    long brow = (long)zi.b*SEQ + zi.c*CHUNK;
    const __half* Ag = g_LG + (long)z*CHUNK*CHUNK + (long)bm*CHUNK;
    const __half* Bg = g_xdt_h + brow*D_INNER + zi.h*HEADDIM;
    float* Cg = g_y + (brow + bm)*D_INNER + zi.h*HEADDIM;
    int KT = (bm + 128) / 32;
    scan_gemm_core<0,1,0>(Ag, CHUNK, Bg, D_INNER, Cg, D_INNER, KT);
}

__global__ __launch_bounds__(256)
void k_states2()
{
    int z = blockIdx.x;
    ZIdx zi = zdec(z);
    long brow = (long)zi.b*SEQ + zi.c*CHUNK;
    const __half* Ag = g_xdt_h + brow*D_INNER + zi.h*HEADDIM;
    const __half* Bg = g_Bdec + (long)z*CHUNK*D_STATE;
    float* Cg = g_states + (long)z*HEADDIM*D_STATE;
    scan_gemm_core<1,1,1>(Ag, D_INNER, Bg, D_STATE, Cg, D_STATE, CHUNK/32);
}

__global__ __launch_bounds__(256)
void k_yoff2()
{
    int z = blockIdx.x, bm = blockIdx.y * 128;
    ZIdx zi = zdec(z);
    long brow = (long)zi.b*SEQ + zi.c*CHUNK;
    const __half* Ag = g_Cexp + (long)z*CHUNK*D_STATE + (long)bm*D_STATE;
    const __half* Bg = g_sin_h + (long)z*HEADDIM*D_STATE;
    float* Cg = g_y + (brow + bm)*D_INNER + zi.h*HEADDIM;
    scan_gemm_core<0,0,2>(Ag, D_STATE, Bg, D_STATE, Cg, D_INNER, D_STATE/32);
}

// ---------------- prep kernels --------------------------------------------
__global__ __launch_bounds__(256)
void k_prep_xdt()
{
    long i = (long)blockIdx.x * 256 + threadIdx.x;
    long n2 = (long)BATCH*SEQ*D_INNER/2;
    long stride = (long)gridDim.x * 256;
    for (; i < n2; i += stride) {
        long d2 = i % (D_INNER/2);
        long bs = i / (D_INNER/2);
        int d = (int)d2 * 2;
        int h = d >> 7;
        float dt = g_dt[bs*N_HEADS + h];
        float v0 = g_xBC[bs*CONV_DIM + d]     * dt;
        float v1 = g_xBC[bs*CONV_DIM + d + 1] * dt;
        *(__half2*)&g_xdt_h[bs*D_INNER + d] = __floats2half2_rn(v0, v1);
    }
}

__global__ __launch_bounds__(256)
void k_prep_lg()
{
    int z = blockIdx.x, lt = blockIdx.y;
    ZIdx zi = zdec(z);
    int bc = z / N_HEADS;
    const float* cum = g_dAcum + ((long)zi.b*N_HEADS + zi.h)*SEQ + zi.c*CHUNK;
    __shared__ float cs[CHUNK];
    if (threadIdx.x < CHUNK) cs[threadIdx.x] = cum[threadIdx.x];
    __syncthreads();
    const float* G = g_G + (long)bc*CHUNK*CHUNK;
    __half* LG = g_LG + (long)z*CHUNK*CHUNK;
    int tid = threadIdx.x;
    #pragma unroll 4
    for (int j = 0; j < 64; j++) {
        int lin = tid + j*256;
        int l = lt*64 + (lin >> 8);
        int s = lin & 255;
        float v = 0.f;
        if (s <= l) v = G[l*CHUNK + s] * fexp(cs[l] - cs[s]);
        LG[l*CHUNK + s] = __float2half_rn(v);
    }
}

__global__ __launch_bounds__(256)
void k_prep_bc()
{
    int z = blockIdx.x;
    ZIdx zi = zdec(z);
    const float* cum = g_dAcum + ((long)zi.b*N_HEADS + zi.h)*SEQ + zi.c*CHUNK;
    __shared__ float fb[CHUNK], fc[CHUNK];
    if (threadIdx.x < CHUNK) {
        float cl = cum[threadIdx.x];
        fb[threadIdx.x] = fexp(cum[CHUNK-1] - cl);
        fc[threadIdx.x] = fexp(cl);
    }
    __syncthreads();
    long brow = (long)zi.b*SEQ + zi.c*CHUNK;
    __half* Bd = g_Bdec + (long)z*CHUNK*D_STATE;
    __half* Ce = g_Cexp + (long)z*CHUNK*D_STATE;
    int tid = threadIdx.x;
    #pragma unroll 4
    for (int j = 0; j < 128; j++) {
        int lin = tid + j*256;
        int l = lin >> 7, n = lin & 127;
        long bs = brow + l;
        float Bv = __half2float(g_bc_h[bs*(2*D_STATE) + n]);
        float Cv = __half2float(g_bc_h[bs*(2*D_STATE) + D_STATE + n]);
        Bd[lin] = __float2half_rn(Bv * fb[l]);
        Ce[lin] = __float2half_rn(Cv * fc[l]);
    }
}

__global__ __launch_bounds__(256)
void k_tohalf(const float* __restrict__ src, __half* __restrict__ dst, long n2)
{
    long i = (long)blockIdx.x * 256 + threadIdx.x;
    long stride = (long)gridDim.x * 256;
    for (; i < n2; i += stride) {
        float2 v = *reinterpret_cast<const float2*>(src + i*2);
        *reinterpret_cast<__half2*>(dst + i*2) = __floats2half2_rn(v.x, v.y);
    }
}

// ---------------- exact fp32 dt projection + softplus ---------------------
__global__ __launch_bounds__(256)
void k_dtproj(const float* __restrict__ inputs,
              const float* __restrict__ in_proj_w,
              const float* __restrict__ in_proj_b,
              const float* __restrict__ dt_bias)
{
    __shared__ float xs[32][133];
    __shared__ float ws[32][133];
    int t = threadIdx.x;
    long r0 = (long)blockIdx.x * 32;
    int r = t >> 3;
    int hb = (t & 7) * 4;
    const float* Wdt = in_proj_w + (size_t)(D_INNER + CONV_DIM) * DIM;
    float acc[4] = {0.f, 0.f, 0.f, 0.f};
    for (int k0 = 0; k0 < DIM; k0 += 128) {
        #pragma unroll
        for (int i = 0; i < 4; i++) {
            int idx = t + i*256;
            int row = idx >> 5, c4 = (idx & 31) * 4;
            float4 v = *reinterpret_cast<const float4*>(&inputs[(r0+row)*DIM + k0 + c4]);
            xs[row][c4] = v.x; xs[row][c4+1] = v.y; xs[row][c4+2] = v.z; xs[row][c4+3] = v.w;
            float4 w = *reinterpret_cast<const float4*>(&Wdt[(size_t)row*DIM + k0 + c4]);
            ws[row][c4] = w.x; ws[row][c4+1] = w.y; ws[row][c4+2] = w.z; ws[row][c4+3] = w.w;
        }
        __syncthreads();
        #pragma unroll 8
        for (int k = 0; k < 128; k++) {
            float xv = xs[r][k];
            #pragma unroll
            for (int j = 0; j < 4; j++)
                acc[j] = fmaf(xv, ws[hb+j][k], acc[j]);
        }
        __syncthreads();
    }
    #pragma unroll
    for (int j = 0; j < 4; j++) {
        int h = hb + j;
        float x = acc[j] + in_proj_b[D_INNER + CONV_DIM + h] + dt_bias[h];
        g_dt[(r0 + r)*N_HEADS + h] = (x > 20.f) ? x : log1pf(expf(x));
    }
}

// ---------------- causal depthwise conv + SiLU ----------------------------
__global__ __launch_bounds__(256)
void k_conv(const float* __restrict__ conv_w, const float* __restrict__ conv_b)
{
    long i = (long)blockIdx.x * 256 + threadIdx.x;
    if (i >= (long)BATCH*SEQ*CONV_DIM) return;
    int c = (int)(i % CONV_DIM);
    long bs = i / CONV_DIM;
    int s = (int)(bs % SEQ);
    int b = (int)(bs / SEQ);
    float acc = conv_b[c];
    #pragma unroll
    for (int k = 0; k < D_CONV; k++) {
        int sp = s - (D_CONV-1) + k;
        if (sp >= 0)
            acc = fmaf(g_zxbcdt[((long)b*SEQ + sp)*D_IN_PROJ + D_INNER + c],
                       conv_w[c*D_CONV + k], acc);
    }
    float v = acc / (1.f + expf(-acc));
    g_xBC[i] = v;
    if (c >= D_INNER)
        g_bc_h[bs*(2*D_STATE) + (c - D_INNER)] = __float2half_rn(v);
}

// ---------------- chunk-local inclusive cumsum of A*dt --------------------
__global__ __launch_bounds__(CHUNK)
void k_cumsum(const float* __restrict__ A_log)
{
    int bz = blockIdx.x;
    int c = bz % NCHUNK; int bh = bz / NCHUNK;
    int h = bh % N_HEADS; int b = bh / N_HEADS;
    int l = threadIdx.x;
    int sg = c*CHUNK + l;
    float A = -expf(A_log[h]);
    float val = A * g_dt[((long)b*SEQ + sg)*N_HEADS + h];
    __shared__ float buf[CHUNK];
    buf[l] = val; __syncthreads();
    for (int off = 1; off < CHUNK; off <<= 1) {
        float t = (l >= off) ? buf[l-off] : 0.f;
        __syncthreads();
        buf[l] += t;
        __syncthreads();
    }
    g_dAcum[((long)b*N_HEADS + h)*SEQ + sg] = buf[l];
}

// ---------------- inter-chunk recurrence (-> Sin fp16), full-chip ---------
__global__ __launch_bounds__(256)
void k_chunkrec()
{
    int bh = blockIdx.x;
    int h = bh % N_HEADS; int b = bh / N_HEADS;
    const float* cum = g_dAcum + (long)bh*SEQ;
    float csum[NCHUNK];
    #pragma unroll
    for (int c = 0; c < NCHUNK; c++) csum[c] = expf(cum[c*CHUNK + CHUNK-1]);
    int pn0 = blockIdx.y * (HEADDIM*D_STATE/8);
    #pragma unroll
    for (int j = 0; j < (HEADDIM*D_STATE/8)/256; j++) {
        int pn = pn0 + j*256 + threadIdx.x;
        float carry = 0.f;
        #pragma unroll
        for (int c = 0; c < NCHUNK; c++) {
            long z = ((long)b*NCHUNK + c)*N_HEADS + h;
            long idx = z*HEADDIM*D_STATE + pn;
            g_sin_h[idx] = __float2half_rn(carry);
            carry = carry * csum[c] + g_states[idx];
        }
    }
}

// ---------------- gate (y + D*x) * silu(z) + RMSNorm -> fp16 --------------
__global__ __launch_bounds__(256)
void k_gatenorm(const float* __restrict__ norm_w, const float* __restrict__ Dv)
{
    long row = blockIdx.x;
    const float* zrow = g_zxbcdt + row*D_IN_PROJ;
    const float* xrow = g_xBC + row*CONV_DIM;
    float* yrow = g_y + row*D_INNER;
    __half* yh = g_y_h + row*D_INNER;
    float vals[16];
    float local = 0.f;
    #pragma unroll
    for (int i = 0; i < 16; i++) {
        int d = threadIdx.x + i*256;
        float z = zrow[d];
        float v = (yrow[d] + Dv[d >> 7] * xrow[d]) * (z / (1.f + expf(-z)));
        vals[i] = v;
        local += v * v;
    }
    __shared__ float red[256];
    red[threadIdx.x] = local; __syncthreads();
    for (int off = 128; off > 0; off >>= 1) {
        if (threadIdx.x < off) red[threadIdx.x] += red[threadIdx.x + off];
        __syncthreads();
    }
    float scale = rsqrtf(red[0] / D_INNER + EPS);
    #pragma unroll
    for (int i = 0; i < 16; i++) {
        int d = threadIdx.x + i*256;
        yh[d] = __float2half_rn(vals[i] * scale * norm_w[d]);
    }
}

// --------------------------------------------------------------------------
extern "C" void kernel_launch(void* const* d_in, const int* in_sizes, int n_in,
                              void* d_out, int out_size)
{
    const float* inputs     = (const float*)d_in[0];
    const float* in_proj_w  = (const float*)d_in[1];
    const float* in_proj_b  = (const float*)d_in[2];
    const float* out_proj_w = (const float*)d_in[3];
    const float* out_proj_b = (const float*)d_in[4];
    const float* conv_w     = (const float*)d_in[5];
    const float* conv_b     = (const float*)d_in[6];
    const float* dt_bias    = (const float*)d_in[7];
    const float* A_log      = (const float*)d_in[8];
    const float* Dv         = (const float*)d_in[9];
    const float* norm_w     = (const float*)d_in[10];
    float* out = (float*)d_out;

    float *zx, *Gp;
    __half *inh, *winh, *wouth, *yh, *bch;
    cudaGetSymbolAddress((void**)&zx,    g_zxbcdt);
    cudaGetSymbolAddress((void**)&Gp,    g_G);
    cudaGetSymbolAddress((void**)&inh,   g_in_h);
    cudaGetSymbolAddress((void**)&winh,  g_win_h);
    cudaGetSymbolAddress((void**)&wouth, g_wout_h);
    cudaGetSymbolAddress((void**)&yh,    g_y_h);
    cudaGetSymbolAddress((void**)&bch,   g_bc_h);

    cudaFuncSetAttribute(gemm_h, cudaFuncAttributeMaxDynamicSharedMemorySize, GSMEM);

    const int M = BATCH * SEQ;     // 4096

    // 0) fp16 mirrors
    k_tohalf<<<2048, 256>>>(inputs,     inh,   (long)M*DIM/2);
    k_tohalf<<<2048, 256>>>(in_proj_w,  winh,  (long)D_IN_PROJ*DIM/2);
    k_tohalf<<<2048, 256>>>(out_proj_w, wouth, (long)DIM*D_INNER/2);

    // 1) in_proj
    {
        dim3 grid((D_IN_PROJ + 127)/128, M/128, 1);
        gemm_h<<<grid, 256, GSMEM>>>(inh, DIM, 0, winh, DIM, 0,
                              zx, D_IN_PROJ, 0, M, D_IN_PROJ, DIM, in_proj_b);
    }
    // 2) exact dt projection
    k_dtproj<<<M/32, 256>>>(inputs, in_proj_w, in_proj_b, dt_bias);
    // 3) conv + silu
    k_conv<<<(int)(((long)BATCH*SEQ*CONV_DIM + 255)/256), 256>>>(conv_w, conv_b);
    // 4) cumsum
    k_cumsum<<<BATCH*N_HEADS*NCHUNK, CHUNK>>>(A_log);
    // 5) G = C @ B^T per (b,c)
    {
        dim3 grid(CHUNK/128, CHUNK/128, BATCH*NCHUNK);
        gemm_h<<<grid, 256, GSMEM>>>(bch + D_STATE, 2*D_STATE, (long)CHUNK*2*D_STATE,
                              bch,           2*D_STATE, (long)CHUNK*2*D_STATE,
                              Gp, CHUNK, (long)CHUNK*CHUNK,
                              CHUNK, CHUNK, D_STATE, nullptr);
    }
    // 6) preps
    k_prep_xdt<<<2048, 256>>>();
    {
        dim3 grid(NBCH, CHUNK/64);
        k_prep_lg<<<grid, 256>>>();
    }
    k_prep_bc<<<NBCH, 256>>>();
    // 7) Y_diag (tensor)
    {
        dim3 grid(NBCH, CHUNK/128);
        k_ydiag2<<<grid, 256>>>();
    }
    // 8) states (tensor)
    k_states2<<<NBCH, 256>>>();
    // 9) inter-chunk recurrence -> Sin fp16 (full-chip)
    {
        dim3 grid(BATCH*N_HEADS, 8);
        k_chunkrec<<<grid, 256>>>();
    }
    // 10) Y_off += (tensor)
    {
        dim3 grid(NBCH, CHUNK/128);
        k_yoff2<<<grid, 256>>>();
    }
    // 11) gate + D*x + RMSNorm -> fp16
    k_gatenorm<<<BATCH*SEQ, 256>>>(norm_w, Dv);
    // 12) out_proj
    {
        dim3 grid(DIM/128, M/128, 1);
        gemm_h<<<grid, 256, GSMEM>>>(yh, D_INNER, 0, wouth, D_INNER, 0,
                              out, DIM, 0, M, DIM, D_INNER, out_proj_b);
    }
}